// round 16
// baseline (speedup 1.0000x reference)
#include <cuda_runtime.h>
#include <cuda_fp16.h>
#include <math.h>
#include <stdint.h>

// Problem constants
#define BSZ   4
#define TLEN  2048
#define EDIM  1024
#define NHEAD 16
#define DHEAD 64
#define CHK   128
#define NCH   16            // TLEN / CHK
#define MROWS (BSZ*TLEN)    // 8192

// Scratch (device globals; allocation-free rule)
__device__ float g_kv[(size_t)BSZ*NHEAD*NCH*DHEAD*DHEAD];
__device__ __half g_S[(size_t)BSZ*NHEAD*NCH*DHEAD*DHEAD];   // fp16 prefix state
__device__ float g_zk[(size_t)BSZ*NHEAD*NCH*DHEAD];
__device__ float g_Z [(size_t)BSZ*NHEAD*NCH*DHEAD];
// fp16 buffers
__device__ __half g_xh[(size_t)MROWS*EDIM];
__device__ __half g_qh[(size_t)MROWS*EDIM];
__device__ __half g_kh[(size_t)MROWS*EDIM];
__device__ __half g_vh[(size_t)MROWS*EDIM];
__device__ __half g_yh[(size_t)MROWS*EDIM];
__device__ __half g_wh[(size_t)4*EDIM*EDIM];      // Wq,Wk,Wv,Wp fp16

// ---------------------------------------------------------------------------
// helpers
// ---------------------------------------------------------------------------
__device__ __forceinline__ uint32_t smem_u32(const void* p) {
    uint32_t a;
    asm("{ .reg .u64 t; cvta.to.shared.u64 t, %1; cvt.u32.u64 %0, t; }"
        : "=r"(a) : "l"(p));
    return a;
}
#define CP_ASYNC16(dst, src) \
    asm volatile("cp.async.cg.shared.global [%0], [%1], 16;" \
                 :: "r"(dst), "l"(src) : "memory")
#define CP_COMMIT() asm volatile("cp.async.commit_group;" ::: "memory")
#define CP_WAIT(N)  asm volatile("cp.async.wait_group %0;" :: "n"(N) : "memory")
#define LDSM_X4(r0, r1, r2, r3, a) \
    asm volatile("ldmatrix.sync.aligned.m8n8.x4.shared.b16 {%0,%1,%2,%3}, [%4];" \
                 : "=r"(r0), "=r"(r1), "=r"(r2), "=r"(r3) : "r"(a))
#define LDSM_X4_T(r0, r1, r2, r3, a) \
    asm volatile("ldmatrix.sync.aligned.m8n8.x4.trans.shared.b16 {%0,%1,%2,%3}, [%4];" \
                 : "=r"(r0), "=r"(r1), "=r"(r2), "=r"(r3) : "r"(a))
#define MMA16816H(d, a, b0v, b1v) \
    asm volatile("mma.sync.aligned.m16n8k16.row.col.f32.f16.f16.f32 " \
                 "{%0,%1,%2,%3}, {%4,%5,%6,%7}, {%8,%9}, {%0,%1,%2,%3};" \
                 : "+f"((d)[0]), "+f"((d)[1]), "+f"((d)[2]), "+f"((d)[3]) \
                 : "r"((a)[0]), "r"((a)[1]), "r"((a)[2]), "r"((a)[3]), \
                   "r"(b0v), "r"(b1v))

// ---------------------------------------------------------------------------
// merged fp32 -> fp16 casts: x (2M float4) then 4 weights (256K float4 each)
// ---------------------------------------------------------------------------
#define N4X (MROWS * EDIM / 4)          // 2097152
#define N4W (EDIM * EDIM / 4)           // 262144

__global__ void cast_all_kernel(const float* __restrict__ x,
                                const float* __restrict__ W0,
                                const float* __restrict__ W1,
                                const float* __restrict__ W2,
                                const float* __restrict__ W3,
                                __half* __restrict__ xh,
                                __half* __restrict__ wh)
{
    int i = blockIdx.x * blockDim.x + threadIdx.x;
    const float* src;
    __half* dst;
    int off;
    if (i < N4X) {
        src = x; dst = xh; off = i;
    } else {
        int j = i - N4X;
        if (j >= 4 * N4W) return;
        int w = j / N4W;
        off = j - w * N4W;
        src = (w == 0) ? W0 : (w == 1) ? W1 : (w == 2) ? W2 : W3;
        dst = wh + (size_t)w * EDIM * EDIM;
    }
    float4 v = ((const float4*)src)[off];
    ((__half2*)dst)[2 * off + 0] = __floats2half2_rn(v.x, v.y);
    ((__half2*)dst)[2 * off + 1] = __floats2half2_rn(v.z, v.w);
}

// ---------------------------------------------------------------------------
// mma.sync fp16 GEMM (NT): C[m,n] = sum_k A[m,k]*B[n,k].   (R12 config)
// BM=BN=128, BK=64, 8 warps (2x4), warp tile 64x32, cp.async double-buffer,
// 2 CTAs/SM. QKV=true: batched blockIdx.z (0=q,1=k phi; 2=v), fp16 out only.
// QKV=false: single GEMM, +bias, fp32 out.
// ---------------------------------------------------------------------------
#define BK      64
#define LDT     72                      // BK + 8 pad (fp16 elems)
#define TILEB   (128 * LDT * 2)         // 18432 B per tile
#define NT      (EDIM / BK)             // 16 chunks
#define GEMM_SMEM (2 * 2 * TILEB)       // 73728 B

template <bool QKV>
__global__ void __launch_bounds__(256, 2)
tc_gemm(const __half* __restrict__ Ah, const __half* __restrict__ Wbase,
        const float* __restrict__ bias, float* __restrict__ C,
        __half* __restrict__ H0, __half* __restrict__ H1, __half* __restrict__ H2)
{
    extern __shared__ char smc[];
    const uint32_t sb = smem_u32(smc);
    const int tid = threadIdx.x;
    const int wid = tid >> 5, lane = tid & 31;
    const int m0g = blockIdx.y * 128;
    const int n0g = blockIdx.x * 128;
    const int m_off = (wid & 1) * 64;
    const int n_off = (wid >> 1) * 32;
    const int z = QKV ? blockIdx.z : 0;
    const __half* Bh = Wbase + (size_t)z * EDIM * EDIM;
    __half* C16 = QKV ? ((z == 0) ? H0 : (z == 1) ? H1 : H2) : nullptr;
    const bool phi = QKV && (z < 2);

    uint32_t aoff[4], boff[2];
    #pragma unroll
    for (int mt = 0; mt < 4; ++mt)
        aoff[mt] = (uint32_t)(((m_off + 16 * mt + (lane & 15)) * LDT
                               + (lane >> 4) * 8) * 2);
    #pragma unroll
    for (int p = 0; p < 2; ++p)
        boff[p] = (uint32_t)(((n_off + 16 * p + ((lane >> 4) << 3) + (lane & 7)) * LDT
                              + ((lane >> 3) & 1) * 8) * 2);

    auto stage_tile = [&](const __half* __restrict__ src, int row0,
                          int kc, uint32_t dstbase) {
        #pragma unroll
        for (int j = 0; j < 4; ++j) {
            int u = tid + j * 256;          // 0..1023: 128 rows x 8 segs
            int row = u >> 3, seg = u & 7;
            uint32_t d = dstbase + (uint32_t)((row * LDT + seg * 8) * 2);
            const __half* g = src + (size_t)(row0 + row) * EDIM + kc + seg * 8;
            CP_ASYNC16(d, g);
        }
    };
    auto stage_chunk = [&](int t, int buf) {
        int kc = t * BK;
        uint32_t base = sb + buf * 2 * TILEB;
        stage_tile(Ah, m0g, kc, base);
        stage_tile(Bh, n0g, kc, base + TILEB);
        CP_COMMIT();
    };

    float acc[4][4][4] = {};

    stage_chunk(0, 0);
    for (int t = 0; t < NT; ++t) {
        const int cur = t & 1;
        if (t + 1 < NT) {
            stage_chunk(t + 1, 1 - cur);
            CP_WAIT(1);
        } else {
            CP_WAIT(0);
        }
        __syncthreads();

        const uint32_t base = sb + cur * 2 * TILEB;
        #pragma unroll
        for (int ks = 0; ks < BK; ks += 16) {
            const uint32_t kso = (uint32_t)(ks * 2);
            uint32_t ah[4][4], bh[2][4];
            #pragma unroll
            for (int mt = 0; mt < 4; ++mt)
                LDSM_X4(ah[mt][0], ah[mt][1], ah[mt][2], ah[mt][3],
                        base + aoff[mt] + kso);
            #pragma unroll
            for (int p = 0; p < 2; ++p)
                LDSM_X4(bh[p][0], bh[p][1], bh[p][2], bh[p][3],
                        base + TILEB + boff[p] + kso);
            #pragma unroll
            for (int i = 0; i < 4; ++i)
                #pragma unroll
                for (int j = 0; j < 4; ++j) {
                    const int p = j >> 1, w = (j & 1) * 2;
                    MMA16816H(acc[i][j], ah[i], bh[p][w], bh[p][w + 1]);
                }
        }
        __syncthreads();
    }

    #pragma unroll
    for (int i = 0; i < 4; ++i) {
        const int r = m0g + m_off + 16 * i + (lane >> 2);
        #pragma unroll
        for (int j = 0; j < 4; ++j) {
            const int c = n0g + n_off + 8 * j + ((lane & 3) << 1);
            float v0 = acc[i][j][0], v1 = acc[i][j][1];
            float v2 = acc[i][j][2], v3 = acc[i][j][3];
            if (QKV) {
                if (phi) {
                    v0 = (v0 > 0.f) ? (v0 + 1.f) : __expf(v0);
                    v1 = (v1 > 0.f) ? (v1 + 1.f) : __expf(v1);
                    v2 = (v2 > 0.f) ? (v2 + 1.f) : __expf(v2);
                    v3 = (v3 > 0.f) ? (v3 + 1.f) : __expf(v3);
                }
                *(__half2*)(C16 + (size_t)r * EDIM + c) = __floats2half2_rn(v0, v1);
                *(__half2*)(C16 + (size_t)(r + 8) * EDIM + c) = __floats2half2_rn(v2, v3);
            } else {
                float b0 = bias[c], b1 = bias[c + 1];
                *(float2*)(C + (size_t)r * EDIM + c) = make_float2(v0 + b0, v1 + b1);
                *(float2*)(C + (size_t)(r + 8) * EDIM + c) = make_float2(v2 + b0, v3 + b1);
            }
        }
    }
}

// ---------------------------------------------------------------------------
// Per-chunk kv state via fp16 mma with ldmatrix.trans, cp.async staging.
// ---------------------------------------------------------------------------
__global__ void __launch_bounds__(256)
chunk_kv_mma(const __half* __restrict__ k16, const __half* __restrict__ v16,
             float* __restrict__ kv, float* __restrict__ zk)
{
    __shared__ __align__(16) __half sKr[128 * 72];
    __shared__ __align__(16) __half sVr[128 * 72];
    const uint32_t sbK = smem_u32(sKr);
    const uint32_t sbV = smem_u32(sVr);

    const int n = blockIdx.x, h = blockIdx.y, b = blockIdx.z;
    const int tid = threadIdx.x;
    const int wid = tid >> 5, lane = tid & 31;
    const int m_off = (wid & 1) * 32;       // d
    const int n_off = (wid >> 1) * 16;      // e
    const size_t rowbase = ((size_t)(b * TLEN + n * CHK)) * EDIM + h * DHEAD;

    // cp.async row-major staging: 128 rows x 64 halves (8 x 16B per row)
    #pragma unroll
    for (int it = 0; it < 4; ++it) {
        int u = tid + it * 256;             // 0..1023
        int row = u >> 3, seg = u & 7;
        const __half* g = k16 + rowbase + (size_t)row * EDIM + seg * 8;
        const __half* g2 = v16 + rowbase + (size_t)row * EDIM + seg * 8;
        CP_ASYNC16(sbK + (uint32_t)((row * 72 + seg * 8) * 2), g);
        CP_ASYNC16(sbV + (uint32_t)((row * 72 + seg * 8) * 2), g2);
    }
    CP_COMMIT();
    CP_WAIT(0);
    __syncthreads();

    if (tid < DHEAD) {
        float z = 0.f;
        #pragma unroll 8
        for (int c = 0; c < CHK; ++c) z += __half2float(sKr[c * 72 + tid]);
        zk[((size_t)((b * NHEAD + h) * NCH) + n) * DHEAD + tid] = z;
    }

    // trans-fragment offsets (bytes), add ks*144 per k-step
    uint32_t aoffT[2];
    #pragma unroll
    for (int mt = 0; mt < 2; ++mt)
        aoffT[mt] = (uint32_t)(((((lane >> 4) & 1) * 8 + (lane & 7)) * 72
                                + m_off + 16 * mt + ((lane >> 3) & 1) * 8) * 2);
    const uint32_t boffT = (uint32_t)(((((lane >> 3) & 1) * 8 + (lane & 7)) * 72
                                      + n_off + ((lane >> 4) & 1) * 8) * 2);

    float acc[2][2][4] = {};
    #pragma unroll
    for (int ks = 0; ks < CHK; ks += 16) {
        const uint32_t kb = (uint32_t)(ks * 144);
        uint32_t a[2][4], bv[4];
        #pragma unroll
        for (int mt = 0; mt < 2; ++mt)
            LDSM_X4_T(a[mt][0], a[mt][1], a[mt][2], a[mt][3], sbK + aoffT[mt] + kb);
        LDSM_X4_T(bv[0], bv[1], bv[2], bv[3], sbV + boffT + kb);
        #pragma unroll
        for (int i = 0; i < 2; ++i)
            #pragma unroll
            for (int j2 = 0; j2 < 2; ++j2)
                MMA16816H(acc[i][j2], a[i], bv[2 * j2], bv[2 * j2 + 1]);
    }

    const size_t obase = ((size_t)((b * NHEAD + h) * NCH) + n) * DHEAD * DHEAD;
    #pragma unroll
    for (int i = 0; i < 2; ++i) {
        const int r1 = m_off + 16 * i + (lane >> 2);
        const int r2 = r1 + 8;
        #pragma unroll
        for (int j2 = 0; j2 < 2; ++j2) {
            const int c = n_off + 8 * j2 + ((lane & 3) << 1);
            *(float2*)(kv + obase + (size_t)r1 * DHEAD + c) =
                make_float2(acc[i][j2][0], acc[i][j2][1]);
            *(float2*)(kv + obase + (size_t)r2 * DHEAD + c) =
                make_float2(acc[i][j2][2], acc[i][j2][3]);
        }
    }
}

// ---------------------------------------------------------------------------
// Merged exclusive prefix scans: kv->S hierarchical (4 threads/segment,
// float4 loads, group offsets via warp shuffle; summation order preserved
// -> bit-identical). zk->Z simple fp32.
// ---------------------------------------------------------------------------
#define SCAN1  (BSZ * NHEAD * DHEAD * DHEAD)   // 262144 (also = #threads, 4/seg)
#define SCAN2  (BSZ * NHEAD * DHEAD)           // 4096

__global__ void prefix_scan_all(const float* __restrict__ kv,
                                __half* __restrict__ S,
                                const float* __restrict__ zk,
                                float* __restrict__ Z)
{
    int i = blockIdx.x * blockDim.x + threadIdx.x;
    if (i < SCAN1) {
        const int per = DHEAD * DHEAD;          // 4096
        const int q = per / 4;                  // 1024 segments per (bh)
        const int seg = i >> 2, tg = i & 3;     // 4 threads per segment
        int bh = seg / q;
        int r4 = (seg - bh * q) * 4;
        size_t base = (size_t)bh * NCH * per + r4;
        const int lane = threadIdx.x & 31;
        const int lb = lane & ~3;

        float4 v[4];
        #pragma unroll
        for (int nn = 0; nn < 4; ++nn)
            v[nn] = *(const float4*)(kv + base + (size_t)(tg * 4 + nn) * per);

        float tx = v[0].x + v[1].x + v[2].x + v[3].x;
        float ty = v[0].y + v[1].y + v[2].y + v[3].y;
        float tz = v[0].z + v[1].z + v[2].z + v[3].z;
        float tw = v[0].w + v[1].w + v[2].w + v[3].w;

        // group-exclusive offsets: sum of totals from lanes with tg' < tg,
        // added in tg' order to preserve left-to-right summation
        float a0 = 0.f, a1 = 0.f, a2 = 0.f, a3 = 0.f;
        #pragma unroll
        for (int jj = 0; jj < 3; ++jj) {
            float sx = __shfl_sync(0xFFFFFFFFu, tx, lb + jj);
            float sy = __shfl_sync(0xFFFFFFFFu, ty, lb + jj);
            float sz = __shfl_sync(0xFFFFFFFFu, tz, lb + jj);
            float sw = __shfl_sync(0xFFFFFFFFu, tw, lb + jj);
            if (jj < tg) { a0 += sx; a1 += sy; a2 += sz; a3 += sw; }
        }

        #pragma unroll
        for (int nn = 0; nn < 4; ++nn) {
            __half* dst = S + base + (size_t)(tg * 4 + nn) * per;
            *(__half2*)(dst)     = __floats2half2_rn(a0, a1);
            *(__half2*)(dst + 2) = __floats2half2_rn(a2, a3);
            a0 += v[nn].x; a1 += v[nn].y; a2 += v[nn].z; a3 += v[nn].w;
        }
    } else {
        int j = i - SCAN1;
        if (j >= SCAN2) return;
        const int per = DHEAD;
        int bh = j / per, r = j - bh * per;
        size_t base = (size_t)bh * NCH * per + r;
        float v[NCH];
        #pragma unroll
        for (int nn = 0; nn < NCH; ++nn)
            v[nn] = zk[base + (size_t)nn * per];
        float acc = 0.f;
        #pragma unroll
        for (int nn = 0; nn < NCH; ++nn) {
            Z[base + (size_t)nn * per] = acc;
            acc += v[nn];
        }
    }
}

// ---------------------------------------------------------------------------
// Tensor-core per-chunk attention; cp.async staging (incl. fp16 S), causal
// triangle skip in BOTH passes, 2 CTAs/SM.
// ---------------------------------------------------------------------------
#define SQ_O    0                       // [128][72] fp16
#define SK_O    18432                   // [128][72] fp16
#define SV_O    36864                   // [128][72] fp16 (row-major)
#define SS_O    55296                   // [64][72]  fp16 (row-major, d rows)
#define SA_O    64512                   // [128][136] fp16 masked A
#define SZ_O    99328                   // [64] fp32
#define SDEN_O  99584                   // [128] fp32
#define ATTN_SMEM 100096

__global__ void __launch_bounds__(256, 2)
chunk_attn_mma(const __half* __restrict__ q16, const __half* __restrict__ k16,
               const __half* __restrict__ v16, const __half* __restrict__ Sh,
               const float* __restrict__ Z, __half* __restrict__ y16)
{
    extern __shared__ char smc[];
    const uint32_t sb = smem_u32(smc);
    float* sZ   = (float*)(smc + SZ_O);
    float* sDen = (float*)(smc + SDEN_O);

    const int n = blockIdx.x, h = blockIdx.y, b = blockIdx.z;
    const int tid = threadIdx.x;
    const int wid = tid >> 5, lane = tid & 31;
    const int m_off = (wid & 1) * 64;
    const int n_off = (wid >> 1) * 32;      // pass A (N=128)
    const int n_off2 = (wid >> 1) * 16;     // pass B (N=64)
    const size_t rowbase = ((size_t)(b * TLEN + n * CHK)) * EDIM + h * DHEAD;
    const size_t sbase = ((size_t)((b * NHEAD + h) * NCH) + n) * DHEAD * DHEAD;
    const size_t zbase = ((size_t)((b * NHEAD + h) * NCH) + n) * DHEAD;

    // cp.async stage Q, K, V row-major [128][72]
    #pragma unroll
    for (int it = 0; it < 4; ++it) {
        int u = tid + it * 256;             // 0..1023
        int row = u >> 3, seg = u & 7;
        uint32_t so = (uint32_t)((row * 72 + seg * 8) * 2);
        CP_ASYNC16(sb + SQ_O + so, q16 + rowbase + (size_t)row * EDIM + seg * 8);
        CP_ASYNC16(sb + SK_O + so, k16 + rowbase + (size_t)row * EDIM + seg * 8);
        CP_ASYNC16(sb + SV_O + so, v16 + rowbase + (size_t)row * EDIM + seg * 8);
    }
    // cp.async stage fp16 S [64][72]
    #pragma unroll
    for (int it = 0; it < 2; ++it) {
        int u = tid + it * 256;             // 0..511
        int row = u >> 3, seg = u & 7;
        CP_ASYNC16(sb + SS_O + (uint32_t)((row * 72 + seg * 8) * 2),
                   Sh + sbase + (size_t)row * DHEAD + seg * 8);
    }
    CP_COMMIT();
    if (tid < DHEAD) sZ[tid] = Z[zbase + tid];
    CP_WAIT(0);
    __syncthreads();

    // den init: eps + phiq . Z
    if (tid < CHK) {
        float s2 = 1e-6f;
        const __half2* qr = (const __half2*)(smc + SQ_O + tid * 144);
        #pragma unroll
        for (int d2 = 0; d2 < 32; ++d2) {
            float2 qq = __half22float2(qr[d2]);
            s2 += qq.x * sZ[2 * d2] + qq.y * sZ[2 * d2 + 1];
        }
        sDen[tid] = s2;
    }
    __syncthreads();

    // fragment offsets
    uint32_t aoffQ[4], aoffA[4], boffK[2];
    #pragma unroll
    for (int mt = 0; mt < 4; ++mt) {
        int rr = m_off + 16 * mt + (lane & 15);
        aoffQ[mt] = (uint32_t)((rr * 72 + (lane >> 4) * 8) * 2);
        aoffA[mt] = (uint32_t)((rr * 136 + (lane >> 4) * 8) * 2);
    }
    #pragma unroll
    for (int p = 0; p < 2; ++p)
        boffK[p] = (uint32_t)(((n_off + 16 * p + ((lane >> 4) << 3) + (lane & 7)) * 72
                               + ((lane >> 3) & 1) * 8) * 2);
    const uint32_t boffT = (uint32_t)(((((lane >> 3) & 1) * 8 + (lane & 7)) * 72
                                      + n_off2 + ((lane >> 4) & 1) * 8) * 2);

    // ---- Pass A: A = Q K^T (128x128, k=64), causal triangle skip ----
    {
        float acc[4][4][4] = {};
        #pragma unroll
        for (int ks = 0; ks < DHEAD; ks += 16) {
            const uint32_t kso = (uint32_t)(ks * 2);
            uint32_t a[4][4], bk[2][4];
            #pragma unroll
            for (int mt = 0; mt < 4; ++mt)
                if (n_off <= m_off + 16 * mt + 15)           // row strip has live tiles
                    LDSM_X4(a[mt][0], a[mt][1], a[mt][2], a[mt][3],
                            sb + SQ_O + aoffQ[mt] + kso);
            #pragma unroll
            for (int p = 0; p < 2; ++p)
                if (n_off + 16 * p <= m_off + 63)            // col strip has live tiles
                    LDSM_X4(bk[p][0], bk[p][1], bk[p][2], bk[p][3],
                            sb + SK_O + boffK[p] + kso);
            #pragma unroll
            for (int i = 0; i < 4; ++i)
                #pragma unroll
                for (int j = 0; j < 4; ++j) {
                    if (n_off + 8 * j > m_off + 16 * i + 15) continue;  // fully masked
                    const int p = j >> 1, w = (j & 1) * 2;
                    MMA16816H(acc[i][j], a[i], bk[p][w], bk[p][w + 1]);
                }
        }
        #pragma unroll
        for (int i = 0; i < 4; ++i) {
            const int r1 = m_off + 16 * i + (lane >> 2);
            const int r2 = r1 + 8;
            float rs1 = 0.f, rs2 = 0.f;
            #pragma unroll
            for (int j = 0; j < 4; ++j) {
                const int c = n_off + 8 * j + ((lane & 3) << 1);
                float v0 = (c <= r1) ? acc[i][j][0] : 0.f;
                float v1 = (c + 1 <= r1) ? acc[i][j][1] : 0.f;
                float v2 = (c <= r2) ? acc[i][j][2] : 0.f;
                float v3 = (c + 1 <= r2) ? acc[i][j][3] : 0.f;
                rs1 += v0 + v1; rs2 += v2 + v3;
                *(__half2*)(smc + SA_O + (r1 * 136 + c) * 2) = __floats2half2_rn(v0, v1);
                *(__half2*)(smc + SA_O + (r2 * 136 + c) * 2) = __floats2half2_rn(v2, v3);
            }
            rs1 += __shfl_xor_sync(0xFFFFFFFFu, rs1, 1);
            rs1 += __shfl_xor_sync(0xFFFFFFFFu, rs1, 2);
            rs2 += __shfl_xor_sync(0xFFFFFFFFu, rs2, 1);
            rs2 += __shfl_xor_sync(0xFFFFFFFFu, rs2, 2);
            if ((lane & 3) == 0) {
                atomicAdd(&sDen[r1], rs1);
                atomicAdd(&sDen[r2], rs2);
            }
        }
    }
    __syncthreads();

    // ---- Pass B: num = A.V + Q.S (128x64), trans B-operands,
    //      causal skip on A.V (A[r][s]=0 for s>r) ----
    {
        float acc2[4][2][4] = {};
        #pragma unroll
        for (int ks = 0; ks < CHK; ks += 16) {        // A.V, k = s = 128
            const uint32_t kso = (uint32_t)(ks * 2);
            const uint32_t kb = (uint32_t)(ks * 144);
            uint32_t a[4][4], bv[4];
            #pragma unroll
            for (int mt = 0; mt < 4; ++mt)
                if (ks <= m_off + 16 * mt + 15)           // strip has nonzero A
                    LDSM_X4(a[mt][0], a[mt][1], a[mt][2], a[mt][3],
                            sb + SA_O + aoffA[mt] + kso);
            if (ks <= m_off + 63)                          // any row tile live
                LDSM_X4_T(bv[0], bv[1], bv[2], bv[3], sb + SV_O + boffT + kb);
            #pragma unroll
            for (int i = 0; i < 4; ++i) {
                if (ks > m_off + 16 * i + 15) continue;   // all-zero A fragment
                #pragma unroll
                for (int j2 = 0; j2 < 2; ++j2)
                    MMA16816H(acc2[i][j2], a[i], bv[2 * j2], bv[2 * j2 + 1]);
            }
        }
        #pragma unroll
        for (int ks = 0; ks < DHEAD; ks += 16) {      // Q.S, k = d = 64
            const uint32_t kso = (uint32_t)(ks * 2);
            const uint32_t kb = (uint32_t)(ks * 144);
            uint32_t a[4][4], bs[4];
            #pragma unroll
            for (int mt = 0; mt < 4; ++mt)
                LDSM_X4(a[mt][0], a[mt][1], a[mt][2], a[mt][3],
                        sb + SQ_O + aoffQ[mt] + kso);
            LDSM_X4_T(bs[0], bs[1], bs[2], bs[3], sb + SS_O + boffT + kb);
            #pragma unroll
            for (int i = 0; i < 4; ++i)
                #pragma unroll
                for (int j2 = 0; j2 < 2; ++j2)
                    MMA16816H(acc2[i][j2], a[i], bs[2 * j2], bs[2 * j2 + 1]);
        }
        #pragma unroll
        for (int i = 0; i < 4; ++i) {
            const int r1 = m_off + 16 * i + (lane >> 2);
            const int r2 = r1 + 8;
            const float inv1 = 1.0f / sDen[r1];
            const float inv2 = 1.0f / sDen[r2];
            #pragma unroll
            for (int j2 = 0; j2 < 2; ++j2) {
                const int c = n_off2 + 8 * j2 + ((lane & 3) << 1);
                *(__half2*)(y16 + rowbase + (size_t)r1 * EDIM + c) =
                    __floats2half2_rn(acc2[i][j2][0] * inv1, acc2[i][j2][1] * inv1);
                *(__half2*)(y16 + rowbase + (size_t)r2 * EDIM + c) =
                    __floats2half2_rn(acc2[i][j2][2] * inv2, acc2[i][j2][3] * inv2);
            }
        }
    }
}

// ---------------------------------------------------------------------------
extern "C" void kernel_launch(void* const* d_in, const int* in_sizes, int n_in,
                              void* d_out, int out_size)
{
    const float* x  = (const float*)d_in[0];
    const float* Wq = (const float*)d_in[1];
    const float* Wk = (const float*)d_in[2];
    const float* Wv = (const float*)d_in[3];
    const float* Wp = (const float*)d_in[4];
    const float* bp = (const float*)d_in[5];
    float* out = (float*)d_out;

    float *kv, *zk, *Z;
    __half *S, *xh, *qh, *kh, *vh, *yh, *wh;
    cudaGetSymbolAddress((void**)&kv, g_kv);
    cudaGetSymbolAddress((void**)&S,  g_S);
    cudaGetSymbolAddress((void**)&zk, g_zk);
    cudaGetSymbolAddress((void**)&Z,  g_Z);
    cudaGetSymbolAddress((void**)&xh, g_xh);
    cudaGetSymbolAddress((void**)&qh, g_qh);
    cudaGetSymbolAddress((void**)&kh, g_kh);
    cudaGetSymbolAddress((void**)&vh, g_vh);
    cudaGetSymbolAddress((void**)&yh, g_yh);
    cudaGetSymbolAddress((void**)&wh, g_wh);

    cudaFuncSetAttribute(tc_gemm<true>,  cudaFuncAttributeMaxDynamicSharedMemorySize, GEMM_SMEM);
    cudaFuncSetAttribute(tc_gemm<false>, cudaFuncAttributeMaxDynamicSharedMemorySize, GEMM_SMEM);
    cudaFuncSetAttribute(chunk_attn_mma,
                         cudaFuncAttributeMaxDynamicSharedMemorySize, ATTN_SMEM);

    const size_t WSZ = (size_t)EDIM * EDIM;

    const int castN = N4X + 4 * N4W;
    cast_all_kernel<<<(castN + 255) / 256, 256>>>(x, Wq, Wk, Wv, Wp, xh, wh);

    dim3 gq(EDIM / 128, MROWS / 128, 3);   // batched q/k/v, fp16-only outputs
    tc_gemm<true><<<gq, 256, GEMM_SMEM>>>(xh, wh, nullptr, nullptr, qh, kh, vh);

    chunk_kv_mma<<<dim3(NCH, NHEAD, BSZ), 256>>>(kh, vh, kv, zk);

    const int scanN = SCAN1 + SCAN2;
    prefix_scan_all<<<(scanN + 255) / 256, 256>>>(kv, S, zk, Z);

    chunk_attn_mma<<<dim3(NCH, NHEAD, BSZ), 256, ATTN_SMEM>>>(qh, kh, vh, S, Z, yh);

    dim3 gp(EDIM / 128, MROWS / 128);      // final projection (1-pass fp16)
    tc_gemm<false><<<gp, 256, GEMM_SMEM>>>(yh, wh + 3 * WSZ, bp, out,
                                           nullptr, nullptr, nullptr);
}

// round 17
// speedup vs baseline: 1.0007x; 1.0007x over previous
#include <cuda_runtime.h>
#include <cuda_fp16.h>
#include <math.h>
#include <stdint.h>

// Problem constants
#define BSZ   4
#define TLEN  2048
#define EDIM  1024
#define NHEAD 16
#define DHEAD 64
#define CHK   128
#define NCH   16            // TLEN / CHK
#define MROWS (BSZ*TLEN)    // 8192

// Scratch (device globals; allocation-free rule)
__device__ float g_kv[(size_t)BSZ*NHEAD*NCH*DHEAD*DHEAD];
__device__ __half g_S[(size_t)BSZ*NHEAD*NCH*DHEAD*DHEAD];   // fp16 prefix state
__device__ float g_zk[(size_t)BSZ*NHEAD*NCH*DHEAD];
__device__ float g_Z [(size_t)BSZ*NHEAD*NCH*DHEAD];
// fp16 buffers
__device__ __half g_xh[(size_t)MROWS*EDIM];
__device__ __half g_qh[(size_t)MROWS*EDIM];
__device__ __half g_kh[(size_t)MROWS*EDIM];
__device__ __half g_vh[(size_t)MROWS*EDIM];
__device__ __half g_yh[(size_t)MROWS*EDIM];
__device__ __half g_wh[(size_t)4*EDIM*EDIM];      // Wq,Wk,Wv,Wp fp16

// ---------------------------------------------------------------------------
// helpers
// ---------------------------------------------------------------------------
__device__ __forceinline__ uint32_t smem_u32(const void* p) {
    uint32_t a;
    asm("{ .reg .u64 t; cvta.to.shared.u64 t, %1; cvt.u32.u64 %0, t; }"
        : "=r"(a) : "l"(p));
    return a;
}
#define CP_ASYNC16(dst, src) \
    asm volatile("cp.async.cg.shared.global [%0], [%1], 16;" \
                 :: "r"(dst), "l"(src) : "memory")
#define CP_COMMIT() asm volatile("cp.async.commit_group;" ::: "memory")
#define CP_WAIT(N)  asm volatile("cp.async.wait_group %0;" :: "n"(N) : "memory")
#define LDSM_X4(r0, r1, r2, r3, a) \
    asm volatile("ldmatrix.sync.aligned.m8n8.x4.shared.b16 {%0,%1,%2,%3}, [%4];" \
                 : "=r"(r0), "=r"(r1), "=r"(r2), "=r"(r3) : "r"(a))
#define LDSM_X4_T(r0, r1, r2, r3, a) \
    asm volatile("ldmatrix.sync.aligned.m8n8.x4.trans.shared.b16 {%0,%1,%2,%3}, [%4];" \
                 : "=r"(r0), "=r"(r1), "=r"(r2), "=r"(r3) : "r"(a))
#define MMA16816H(d, a, b0v, b1v) \
    asm volatile("mma.sync.aligned.m16n8k16.row.col.f32.f16.f16.f32 " \
                 "{%0,%1,%2,%3}, {%4,%5,%6,%7}, {%8,%9}, {%0,%1,%2,%3};" \
                 : "+f"((d)[0]), "+f"((d)[1]), "+f"((d)[2]), "+f"((d)[3]) \
                 : "r"((a)[0]), "r"((a)[1]), "r"((a)[2]), "r"((a)[3]), \
                   "r"(b0v), "r"(b1v))

// ---------------------------------------------------------------------------
// merged fp32 -> fp16 casts: x (2M float4) then 4 weights (256K float4 each)
// ---------------------------------------------------------------------------
#define N4X (MROWS * EDIM / 4)          // 2097152
#define N4W (EDIM * EDIM / 4)           // 262144

__global__ void cast_all_kernel(const float* __restrict__ x,
                                const float* __restrict__ W0,
                                const float* __restrict__ W1,
                                const float* __restrict__ W2,
                                const float* __restrict__ W3,
                                __half* __restrict__ xh,
                                __half* __restrict__ wh)
{
    int i = blockIdx.x * blockDim.x + threadIdx.x;
    const float* src;
    __half* dst;
    int off;
    if (i < N4X) {
        src = x; dst = xh; off = i;
    } else {
        int j = i - N4X;
        if (j >= 4 * N4W) return;
        int w = j / N4W;
        off = j - w * N4W;
        src = (w == 0) ? W0 : (w == 1) ? W1 : (w == 2) ? W2 : W3;
        dst = wh + (size_t)w * EDIM * EDIM;
    }
    float4 v = ((const float4*)src)[off];
    ((__half2*)dst)[2 * off + 0] = __floats2half2_rn(v.x, v.y);
    ((__half2*)dst)[2 * off + 1] = __floats2half2_rn(v.z, v.w);
}

// ---------------------------------------------------------------------------
// mma.sync fp16 GEMM (NT): C[m,n] = sum_k A[m,k]*B[n,k].   (R12 config)
// BM=BN=128, BK=64, 8 warps (2x4), warp tile 64x32, cp.async double-buffer,
// 2 CTAs/SM. QKV=true: batched blockIdx.z (0=q,1=k phi; 2=v), fp16 out only.
// QKV=false: single GEMM, +bias, fp32 out.
// ---------------------------------------------------------------------------
#define BK      64
#define LDT     72                      // BK + 8 pad (fp16 elems)
#define TILEB   (128 * LDT * 2)         // 18432 B per tile
#define NT      (EDIM / BK)             // 16 chunks
#define GEMM_SMEM (2 * 2 * TILEB)       // 73728 B

template <bool QKV>
__global__ void __launch_bounds__(256, 2)
tc_gemm(const __half* __restrict__ Ah, const __half* __restrict__ Wbase,
        const float* __restrict__ bias, float* __restrict__ C,
        __half* __restrict__ H0, __half* __restrict__ H1, __half* __restrict__ H2)
{
    extern __shared__ char smc[];
    const uint32_t sb = smem_u32(smc);
    const int tid = threadIdx.x;
    const int wid = tid >> 5, lane = tid & 31;
    const int m0g = blockIdx.y * 128;
    const int n0g = blockIdx.x * 128;
    const int m_off = (wid & 1) * 64;
    const int n_off = (wid >> 1) * 32;
    const int z = QKV ? blockIdx.z : 0;
    const __half* Bh = Wbase + (size_t)z * EDIM * EDIM;
    __half* C16 = QKV ? ((z == 0) ? H0 : (z == 1) ? H1 : H2) : nullptr;
    const bool phi = QKV && (z < 2);

    uint32_t aoff[4], boff[2];
    #pragma unroll
    for (int mt = 0; mt < 4; ++mt)
        aoff[mt] = (uint32_t)(((m_off + 16 * mt + (lane & 15)) * LDT
                               + (lane >> 4) * 8) * 2);
    #pragma unroll
    for (int p = 0; p < 2; ++p)
        boff[p] = (uint32_t)(((n_off + 16 * p + ((lane >> 4) << 3) + (lane & 7)) * LDT
                              + ((lane >> 3) & 1) * 8) * 2);

    auto stage_tile = [&](const __half* __restrict__ src, int row0,
                          int kc, uint32_t dstbase) {
        #pragma unroll
        for (int j = 0; j < 4; ++j) {
            int u = tid + j * 256;          // 0..1023: 128 rows x 8 segs
            int row = u >> 3, seg = u & 7;
            uint32_t d = dstbase + (uint32_t)((row * LDT + seg * 8) * 2);
            const __half* g = src + (size_t)(row0 + row) * EDIM + kc + seg * 8;
            CP_ASYNC16(d, g);
        }
    };
    auto stage_chunk = [&](int t, int buf) {
        int kc = t * BK;
        uint32_t base = sb + buf * 2 * TILEB;
        stage_tile(Ah, m0g, kc, base);
        stage_tile(Bh, n0g, kc, base + TILEB);
        CP_COMMIT();
    };

    float acc[4][4][4] = {};

    stage_chunk(0, 0);
    for (int t = 0; t < NT; ++t) {
        const int cur = t & 1;
        if (t + 1 < NT) {
            stage_chunk(t + 1, 1 - cur);
            CP_WAIT(1);
        } else {
            CP_WAIT(0);
        }
        __syncthreads();

        const uint32_t base = sb + cur * 2 * TILEB;
        #pragma unroll
        for (int ks = 0; ks < BK; ks += 16) {
            const uint32_t kso = (uint32_t)(ks * 2);
            uint32_t ah[4][4], bh[2][4];
            #pragma unroll
            for (int mt = 0; mt < 4; ++mt)
                LDSM_X4(ah[mt][0], ah[mt][1], ah[mt][2], ah[mt][3],
                        base + aoff[mt] + kso);
            #pragma unroll
            for (int p = 0; p < 2; ++p)
                LDSM_X4(bh[p][0], bh[p][1], bh[p][2], bh[p][3],
                        base + TILEB + boff[p] + kso);
            #pragma unroll
            for (int i = 0; i < 4; ++i)
                #pragma unroll
                for (int j = 0; j < 4; ++j) {
                    const int p = j >> 1, w = (j & 1) * 2;
                    MMA16816H(acc[i][j], ah[i], bh[p][w], bh[p][w + 1]);
                }
        }
        __syncthreads();
    }

    #pragma unroll
    for (int i = 0; i < 4; ++i) {
        const int r = m0g + m_off + 16 * i + (lane >> 2);
        #pragma unroll
        for (int j = 0; j < 4; ++j) {
            const int c = n0g + n_off + 8 * j + ((lane & 3) << 1);
            float v0 = acc[i][j][0], v1 = acc[i][j][1];
            float v2 = acc[i][j][2], v3 = acc[i][j][3];
            if (QKV) {
                if (phi) {
                    v0 = (v0 > 0.f) ? (v0 + 1.f) : __expf(v0);
                    v1 = (v1 > 0.f) ? (v1 + 1.f) : __expf(v1);
                    v2 = (v2 > 0.f) ? (v2 + 1.f) : __expf(v2);
                    v3 = (v3 > 0.f) ? (v3 + 1.f) : __expf(v3);
                }
                *(__half2*)(C16 + (size_t)r * EDIM + c) = __floats2half2_rn(v0, v1);
                *(__half2*)(C16 + (size_t)(r + 8) * EDIM + c) = __floats2half2_rn(v2, v3);
            } else {
                float b0 = bias[c], b1 = bias[c + 1];
                *(float2*)(C + (size_t)r * EDIM + c) = make_float2(v0 + b0, v1 + b1);
                *(float2*)(C + (size_t)(r + 8) * EDIM + c) = make_float2(v2 + b0, v3 + b1);
            }
        }
    }
}

// ---------------------------------------------------------------------------
// Per-chunk kv state via fp16 mma with ldmatrix.trans, cp.async staging.
// zk rowsum moved after mma issue so it overlaps tensor work.
// ---------------------------------------------------------------------------
__global__ void __launch_bounds__(256)
chunk_kv_mma(const __half* __restrict__ k16, const __half* __restrict__ v16,
             float* __restrict__ kv, float* __restrict__ zk)
{
    __shared__ __align__(16) __half sKr[128 * 72];
    __shared__ __align__(16) __half sVr[128 * 72];
    const uint32_t sbK = smem_u32(sKr);
    const uint32_t sbV = smem_u32(sVr);

    const int n = blockIdx.x, h = blockIdx.y, b = blockIdx.z;
    const int tid = threadIdx.x;
    const int wid = tid >> 5, lane = tid & 31;
    const int m_off = (wid & 1) * 32;       // d
    const int n_off = (wid >> 1) * 16;      // e
    const size_t rowbase = ((size_t)(b * TLEN + n * CHK)) * EDIM + h * DHEAD;

    // cp.async row-major staging: 128 rows x 64 halves (8 x 16B per row)
    #pragma unroll
    for (int it = 0; it < 4; ++it) {
        int u = tid + it * 256;             // 0..1023
        int row = u >> 3, seg = u & 7;
        const __half* g = k16 + rowbase + (size_t)row * EDIM + seg * 8;
        const __half* g2 = v16 + rowbase + (size_t)row * EDIM + seg * 8;
        CP_ASYNC16(sbK + (uint32_t)((row * 72 + seg * 8) * 2), g);
        CP_ASYNC16(sbV + (uint32_t)((row * 72 + seg * 8) * 2), g2);
    }
    CP_COMMIT();
    CP_WAIT(0);
    __syncthreads();

    // trans-fragment offsets (bytes), add ks*144 per k-step
    uint32_t aoffT[2];
    #pragma unroll
    for (int mt = 0; mt < 2; ++mt)
        aoffT[mt] = (uint32_t)(((((lane >> 4) & 1) * 8 + (lane & 7)) * 72
                                + m_off + 16 * mt + ((lane >> 3) & 1) * 8) * 2);
    const uint32_t boffT = (uint32_t)(((((lane >> 3) & 1) * 8 + (lane & 7)) * 72
                                      + n_off + ((lane >> 4) & 1) * 8) * 2);

    float acc[2][2][4] = {};
    #pragma unroll
    for (int ks = 0; ks < CHK; ks += 16) {
        const uint32_t kb = (uint32_t)(ks * 144);
        uint32_t a[2][4], bv[4];
        #pragma unroll
        for (int mt = 0; mt < 2; ++mt)
            LDSM_X4_T(a[mt][0], a[mt][1], a[mt][2], a[mt][3], sbK + aoffT[mt] + kb);
        LDSM_X4_T(bv[0], bv[1], bv[2], bv[3], sbV + boffT + kb);
        #pragma unroll
        for (int i = 0; i < 2; ++i)
            #pragma unroll
            for (int j2 = 0; j2 < 2; ++j2)
                MMA16816H(acc[i][j2], a[i], bv[2 * j2], bv[2 * j2 + 1]);
    }

    // zk rowsum (after mma issue; overlaps tensor pipe drain)
    if (tid < DHEAD) {
        float z = 0.f;
        #pragma unroll 8
        for (int c = 0; c < CHK; ++c) z += __half2float(sKr[c * 72 + tid]);
        zk[((size_t)((b * NHEAD + h) * NCH) + n) * DHEAD + tid] = z;
    }

    const size_t obase = ((size_t)((b * NHEAD + h) * NCH) + n) * DHEAD * DHEAD;
    #pragma unroll
    for (int i = 0; i < 2; ++i) {
        const int r1 = m_off + 16 * i + (lane >> 2);
        const int r2 = r1 + 8;
        #pragma unroll
        for (int j2 = 0; j2 < 2; ++j2) {
            const int c = n_off + 8 * j2 + ((lane & 3) << 1);
            *(float2*)(kv + obase + (size_t)r1 * DHEAD + c) =
                make_float2(acc[i][j2][0], acc[i][j2][1]);
            *(float2*)(kv + obase + (size_t)r2 * DHEAD + c) =
                make_float2(acc[i][j2][2], acc[i][j2][3]);
        }
    }
}

// ---------------------------------------------------------------------------
// Merged exclusive prefix scans: kv->S vectorized float4/thread (R15 form),
// S written fp16; zk->Z fp32.
// ---------------------------------------------------------------------------
#define SCAN1  (BSZ * NHEAD * DHEAD * DHEAD)   // 262144
#define SCAN1T (SCAN1 / 4)                     // 65536 float4 threads
#define SCAN2  (BSZ * NHEAD * DHEAD)           // 4096

__global__ void prefix_scan_all(const float* __restrict__ kv,
                                __half* __restrict__ S,
                                const float* __restrict__ zk,
                                float* __restrict__ Z)
{
    int i = blockIdx.x * blockDim.x + threadIdx.x;
    if (i < SCAN1T) {
        const int per = DHEAD * DHEAD;          // 4096
        const int q = per / 4;                  // 1024
        int bh = i / q;
        int r4 = (i - bh * q) * 4;
        size_t base = (size_t)bh * NCH * per + r4;
        float4 v[NCH];
        #pragma unroll
        for (int nn = 0; nn < NCH; ++nn)
            v[nn] = *(const float4*)(kv + base + (size_t)nn * per);
        float a0 = 0.f, a1 = 0.f, a2 = 0.f, a3 = 0.f;
        #pragma unroll
        for (int nn = 0; nn < NCH; ++nn) {
            __half* dst = S + base + (size_t)nn * per;
            *(__half2*)(dst)     = __floats2half2_rn(a0, a1);
            *(__half2*)(dst + 2) = __floats2half2_rn(a2, a3);
            a0 += v[nn].x; a1 += v[nn].y; a2 += v[nn].z; a3 += v[nn].w;
        }
    } else {
        int j = i - SCAN1T;
        if (j >= SCAN2) return;
        const int per = DHEAD;
        int bh = j / per, r = j - bh * per;
        size_t base = (size_t)bh * NCH * per + r;
        float v[NCH];
        #pragma unroll
        for (int nn = 0; nn < NCH; ++nn)
            v[nn] = zk[base + (size_t)nn * per];
        float acc = 0.f;
        #pragma unroll
        for (int nn = 0; nn < NCH; ++nn) {
            Z[base + (size_t)nn * per] = acc;
            acc += v[nn];
        }
    }
}

// ---------------------------------------------------------------------------
// Tensor-core per-chunk attention; cp.async staging (incl. fp16 S), causal
// triangle skip in BOTH passes, 2 CTAs/SM.
// ---------------------------------------------------------------------------
#define SQ_O    0                       // [128][72] fp16
#define SK_O    18432                   // [128][72] fp16
#define SV_O    36864                   // [128][72] fp16 (row-major)
#define SS_O    55296                   // [64][72]  fp16 (row-major, d rows)
#define SA_O    64512                   // [128][136] fp16 masked A
#define SZ_O    99328                   // [64] fp32
#define SDEN_O  99584                   // [128] fp32
#define ATTN_SMEM 100096

__global__ void __launch_bounds__(256, 2)
chunk_attn_mma(const __half* __restrict__ q16, const __half* __restrict__ k16,
               const __half* __restrict__ v16, const __half* __restrict__ Sh,
               const float* __restrict__ Z, __half* __restrict__ y16)
{
    extern __shared__ char smc[];
    const uint32_t sb = smem_u32(smc);
    float* sZ   = (float*)(smc + SZ_O);
    float* sDen = (float*)(smc + SDEN_O);

    const int n = blockIdx.x, h = blockIdx.y, b = blockIdx.z;
    const int tid = threadIdx.x;
    const int wid = tid >> 5, lane = tid & 31;
    const int m_off = (wid & 1) * 64;
    const int n_off = (wid >> 1) * 32;      // pass A (N=128)
    const int n_off2 = (wid >> 1) * 16;     // pass B (N=64)
    const size_t rowbase = ((size_t)(b * TLEN + n * CHK)) * EDIM + h * DHEAD;
    const size_t sbase = ((size_t)((b * NHEAD + h) * NCH) + n) * DHEAD * DHEAD;
    const size_t zbase = ((size_t)((b * NHEAD + h) * NCH) + n) * DHEAD;

    // cp.async stage Q, K, V row-major [128][72]
    #pragma unroll
    for (int it = 0; it < 4; ++it) {
        int u = tid + it * 256;             // 0..1023
        int row = u >> 3, seg = u & 7;
        uint32_t so = (uint32_t)((row * 72 + seg * 8) * 2);
        CP_ASYNC16(sb + SQ_O + so, q16 + rowbase + (size_t)row * EDIM + seg * 8);
        CP_ASYNC16(sb + SK_O + so, k16 + rowbase + (size_t)row * EDIM + seg * 8);
        CP_ASYNC16(sb + SV_O + so, v16 + rowbase + (size_t)row * EDIM + seg * 8);
    }
    // cp.async stage fp16 S [64][72]
    #pragma unroll
    for (int it = 0; it < 2; ++it) {
        int u = tid + it * 256;             // 0..511
        int row = u >> 3, seg = u & 7;
        CP_ASYNC16(sb + SS_O + (uint32_t)((row * 72 + seg * 8) * 2),
                   Sh + sbase + (size_t)row * DHEAD + seg * 8);
    }
    CP_COMMIT();
    if (tid < DHEAD) sZ[tid] = Z[zbase + tid];
    CP_WAIT(0);
    __syncthreads();

    // den init: eps + phiq . Z
    if (tid < CHK) {
        float s2 = 1e-6f;
        const __half2* qr = (const __half2*)(smc + SQ_O + tid * 144);
        #pragma unroll
        for (int d2 = 0; d2 < 32; ++d2) {
            float2 qq = __half22float2(qr[d2]);
            s2 += qq.x * sZ[2 * d2] + qq.y * sZ[2 * d2 + 1];
        }
        sDen[tid] = s2;
    }
    __syncthreads();

    // fragment offsets
    uint32_t aoffQ[4], aoffA[4], boffK[2];
    #pragma unroll
    for (int mt = 0; mt < 4; ++mt) {
        int rr = m_off + 16 * mt + (lane & 15);
        aoffQ[mt] = (uint32_t)((rr * 72 + (lane >> 4) * 8) * 2);
        aoffA[mt] = (uint32_t)((rr * 136 + (lane >> 4) * 8) * 2);
    }
    #pragma unroll
    for (int p = 0; p < 2; ++p)
        boffK[p] = (uint32_t)(((n_off + 16 * p + ((lane >> 4) << 3) + (lane & 7)) * 72
                               + ((lane >> 3) & 1) * 8) * 2);
    const uint32_t boffT = (uint32_t)(((((lane >> 3) & 1) * 8 + (lane & 7)) * 72
                                      + n_off2 + ((lane >> 4) & 1) * 8) * 2);

    // ---- Pass A: A = Q K^T (128x128, k=64), causal triangle skip ----
    {
        float acc[4][4][4] = {};
        #pragma unroll
        for (int ks = 0; ks < DHEAD; ks += 16) {
            const uint32_t kso = (uint32_t)(ks * 2);
            uint32_t a[4][4], bk[2][4];
            #pragma unroll
            for (int mt = 0; mt < 4; ++mt)
                if (n_off <= m_off + 16 * mt + 15)           // row strip has live tiles
                    LDSM_X4(a[mt][0], a[mt][1], a[mt][2], a[mt][3],
                            sb + SQ_O + aoffQ[mt] + kso);
            #pragma unroll
            for (int p = 0; p < 2; ++p)
                if (n_off + 16 * p <= m_off + 63)            // col strip has live tiles
                    LDSM_X4(bk[p][0], bk[p][1], bk[p][2], bk[p][3],
                            sb + SK_O + boffK[p] + kso);
            #pragma unroll
            for (int i = 0; i < 4; ++i)
                #pragma unroll
                for (int j = 0; j < 4; ++j) {
                    if (n_off + 8 * j > m_off + 16 * i + 15) continue;  // fully masked
                    const int p = j >> 1, w = (j & 1) * 2;
                    MMA16816H(acc[i][j], a[i], bk[p][w], bk[p][w + 1]);
                }
        }
        #pragma unroll
        for (int i = 0; i < 4; ++i) {
            const int r1 = m_off + 16 * i + (lane >> 2);
            const int r2 = r1 + 8;
            float rs1 = 0.f, rs2 = 0.f;
            #pragma unroll
            for (int j = 0; j < 4; ++j) {
                const int c = n_off + 8 * j + ((lane & 3) << 1);
                float v0 = (c <= r1) ? acc[i][j][0] : 0.f;
                float v1 = (c + 1 <= r1) ? acc[i][j][1] : 0.f;
                float v2 = (c <= r2) ? acc[i][j][2] : 0.f;
                float v3 = (c + 1 <= r2) ? acc[i][j][3] : 0.f;
                rs1 += v0 + v1; rs2 += v2 + v3;
                *(__half2*)(smc + SA_O + (r1 * 136 + c) * 2) = __floats2half2_rn(v0, v1);
                *(__half2*)(smc + SA_O + (r2 * 136 + c) * 2) = __floats2half2_rn(v2, v3);
            }
            rs1 += __shfl_xor_sync(0xFFFFFFFFu, rs1, 1);
            rs1 += __shfl_xor_sync(0xFFFFFFFFu, rs1, 2);
            rs2 += __shfl_xor_sync(0xFFFFFFFFu, rs2, 1);
            rs2 += __shfl_xor_sync(0xFFFFFFFFu, rs2, 2);
            if ((lane & 3) == 0) {
                atomicAdd(&sDen[r1], rs1);
                atomicAdd(&sDen[r2], rs2);
            }
        }
    }
    __syncthreads();

    // ---- Pass B: num = A.V + Q.S (128x64), trans B-operands,
    //      causal skip on A.V (A[r][s]=0 for s>r) ----
    {
        float acc2[4][2][4] = {};
        #pragma unroll
        for (int ks = 0; ks < CHK; ks += 16) {        // A.V, k = s = 128
            const uint32_t kso = (uint32_t)(ks * 2);
            const uint32_t kb = (uint32_t)(ks * 144);
            uint32_t a[4][4], bv[4];
            #pragma unroll
            for (int mt = 0; mt < 4; ++mt)
                if (ks <= m_off + 16 * mt + 15)           // strip has nonzero A
                    LDSM_X4(a[mt][0], a[mt][1], a[mt][2], a[mt][3],
                            sb + SA_O + aoffA[mt] + kso);
            if (ks <= m_off + 63)                          // any row tile live
                LDSM_X4_T(bv[0], bv[1], bv[2], bv[3], sb + SV_O + boffT + kb);
            #pragma unroll
            for (int i = 0; i < 4; ++i) {
                if (ks > m_off + 16 * i + 15) continue;   // all-zero A fragment
                #pragma unroll
                for (int j2 = 0; j2 < 2; ++j2)
                    MMA16816H(acc2[i][j2], a[i], bv[2 * j2], bv[2 * j2 + 1]);
            }
        }
        #pragma unroll
        for (int ks = 0; ks < DHEAD; ks += 16) {      // Q.S, k = d = 64
            const uint32_t kso = (uint32_t)(ks * 2);
            const uint32_t kb = (uint32_t)(ks * 144);
            uint32_t a[4][4], bs[4];
            #pragma unroll
            for (int mt = 0; mt < 4; ++mt)
                LDSM_X4(a[mt][0], a[mt][1], a[mt][2], a[mt][3],
                        sb + SQ_O + aoffQ[mt] + kso);
            LDSM_X4_T(bs[0], bs[1], bs[2], bs[3], sb + SS_O + boffT + kb);
            #pragma unroll
            for (int i = 0; i < 4; ++i)
                #pragma unroll
                for (int j2 = 0; j2 < 2; ++j2)
                    MMA16816H(acc2[i][j2], a[i], bs[2 * j2], bs[2 * j2 + 1]);
        }
        #pragma unroll
        for (int i = 0; i < 4; ++i) {
            const int r1 = m_off + 16 * i + (lane >> 2);
            const int r2 = r1 + 8;
            const float inv1 = 1.0f / sDen[r1];
            const float inv2 = 1.0f / sDen[r2];
            #pragma unroll
            for (int j2 = 0; j2 < 2; ++j2) {
                const int c = n_off2 + 8 * j2 + ((lane & 3) << 1);
                *(__half2*)(y16 + rowbase + (size_t)r1 * EDIM + c) =
                    __floats2half2_rn(acc2[i][j2][0] * inv1, acc2[i][j2][1] * inv1);
                *(__half2*)(y16 + rowbase + (size_t)r2 * EDIM + c) =
                    __floats2half2_rn(acc2[i][j2][2] * inv2, acc2[i][j2][3] * inv2);
            }
        }
    }
}

// ---------------------------------------------------------------------------
extern "C" void kernel_launch(void* const* d_in, const int* in_sizes, int n_in,
                              void* d_out, int out_size)
{
    const float* x  = (const float*)d_in[0];
    const float* Wq = (const float*)d_in[1];
    const float* Wk = (const float*)d_in[2];
    const float* Wv = (const float*)d_in[3];
    const float* Wp = (const float*)d_in[4];
    const float* bp = (const float*)d_in[5];
    float* out = (float*)d_out;

    float *kv, *zk, *Z;
    __half *S, *xh, *qh, *kh, *vh, *yh, *wh;
    cudaGetSymbolAddress((void**)&kv, g_kv);
    cudaGetSymbolAddress((void**)&S,  g_S);
    cudaGetSymbolAddress((void**)&zk, g_zk);
    cudaGetSymbolAddress((void**)&Z,  g_Z);
    cudaGetSymbolAddress((void**)&xh, g_xh);
    cudaGetSymbolAddress((void**)&qh, g_qh);
    cudaGetSymbolAddress((void**)&kh, g_kh);
    cudaGetSymbolAddress((void**)&vh, g_vh);
    cudaGetSymbolAddress((void**)&yh, g_yh);
    cudaGetSymbolAddress((void**)&wh, g_wh);

    cudaFuncSetAttribute(tc_gemm<true>,  cudaFuncAttributeMaxDynamicSharedMemorySize, GEMM_SMEM);
    cudaFuncSetAttribute(tc_gemm<false>, cudaFuncAttributeMaxDynamicSharedMemorySize, GEMM_SMEM);
    cudaFuncSetAttribute(chunk_attn_mma,
                         cudaFuncAttributeMaxDynamicSharedMemorySize, ATTN_SMEM);

    const size_t WSZ = (size_t)EDIM * EDIM;

    const int castN = N4X + 4 * N4W;
    cast_all_kernel<<<(castN + 255) / 256, 256>>>(x, Wq, Wk, Wv, Wp, xh, wh);

    dim3 gq(EDIM / 128, MROWS / 128, 3);   // batched q/k/v, fp16-only outputs
    tc_gemm<true><<<gq, 256, GEMM_SMEM>>>(xh, wh, nullptr, nullptr, qh, kh, vh);

    chunk_kv_mma<<<dim3(NCH, NHEAD, BSZ), 256>>>(kh, vh, kv, zk);

    const int scanN = SCAN1T + SCAN2;
    prefix_scan_all<<<(scanN + 255) / 256, 256>>>(kv, S, zk, Z);

    chunk_attn_mma<<<dim3(NCH, NHEAD, BSZ), 256, ATTN_SMEM>>>(qh, kh, vh, S, Z, yh);

    dim3 gp(EDIM / 128, MROWS / 128);      // final projection (1-pass fp16)
    tc_gemm<false><<<gp, 256, GEMM_SMEM>>>(yh, wh + 3 * WSZ, bp, out,
                                           nullptr, nullptr, nullptr);
}